// round 3
// baseline (speedup 1.0000x reference)
#include <cuda_runtime.h>
#include <cstdint>

#define B_  4
#define S_  4096
#define DM  768
#define DK  64

// Scratch (device globals: no allocation allowed)
__device__ float g_Q [B_ * S_ * DK];   // [b*S+s][d]  (pre-scaled by 1/8)
__device__ float g_Kt[B_ * DK * S_];   // [b][d][s]   (K transposed)
__device__ float g_V [B_ * S_ * DK];   // [b*S+s][d]

// ---------------- packed f32x2 helpers (FFMA2 path, sm_100+) ----------------
__device__ __forceinline__ void fma2(uint64_t& acc, uint64_t a, uint64_t b) {
    asm("fma.rn.f32x2 %0, %1, %2, %0;" : "+l"(acc) : "l"(a), "l"(b));
}
__device__ __forceinline__ void mul2(uint64_t& acc, uint64_t a) {
    asm("mul.rn.f32x2 %0, %0, %1;" : "+l"(acc) : "l"(a));
}
__device__ __forceinline__ uint64_t f2u(float x, float y) {
    uint64_t v; asm("mov.b64 %0, {%1,%2};" : "=l"(v) : "f"(x), "f"(y)); return v;
}
__device__ __forceinline__ float2 u2f(uint64_t v) {
    float2 f; asm("mov.b64 {%0,%1}, %2;" : "=f"(f.x), "=f"(f.y) : "l"(v)); return f;
}

// =====================================================================
// Kernel 1: fused QKV projection. grid = 512, block = 128.
// One block computes a 32-row stripe of Q, K, V together (x read ONCE).
// BK=16, register-prefetch double buffering.
// Thread (ty 0..7, tx 0..15) owns 4 rows x (4 cols per W).
// K is written TRANSPOSED to g_Kt[b][d][s]; Q is pre-scaled by 0.125.
// =====================================================================
#define XS_STRIDE 20    // floats per x row (16 + 4 pad)
#define WS_STRIDE 208   // floats per kk row (3*68 + 4 pad)

__global__ __launch_bounds__(128) void proj_kernel(
    const float* __restrict__ x,
    const float* __restrict__ WQ,
    const float* __restrict__ WK,
    const float* __restrict__ WV)
{
    __shared__ float xs[32 * XS_STRIDE];   // [r][kk]
    __shared__ float ws[16 * WS_STRIDE];   // [kk][w*68 + n]

    const int tid = threadIdx.x;
    const int ty = tid >> 4;        // 0..7  -> rows ty*4..+3
    const int tx = tid & 15;        // 0..15 -> cols tx*4..+3
    const int row0 = blockIdx.x * 32;

    const float* __restrict__ Wp0 = WQ;
    const float* __restrict__ Wp1 = WK;
    const float* __restrict__ Wp2 = WV;

    // prefetch indices
    const int xr_r = tid >> 2, xr_c = tid & 3;        // x: 32 rows x 4 float4
    const int w_kk0 = tid >> 4, w_kk1 = (tid + 128) >> 4, w_n4 = tid & 15; // W: 16kk x 16 float4

    float4 xr = *reinterpret_cast<const float4*>(&x[(row0 + xr_r) * DM + xr_c * 4]);
    float4 wr0a = *reinterpret_cast<const float4*>(&Wp0[w_kk0 * DK + w_n4 * 4]);
    float4 wr0b = *reinterpret_cast<const float4*>(&Wp0[w_kk1 * DK + w_n4 * 4]);
    float4 wr1a = *reinterpret_cast<const float4*>(&Wp1[w_kk0 * DK + w_n4 * 4]);
    float4 wr1b = *reinterpret_cast<const float4*>(&Wp1[w_kk1 * DK + w_n4 * 4]);
    float4 wr2a = *reinterpret_cast<const float4*>(&Wp2[w_kk0 * DK + w_n4 * 4]);
    float4 wr2b = *reinterpret_cast<const float4*>(&Wp2[w_kk1 * DK + w_n4 * 4]);

    uint64_t acc[3][4][2];
#pragma unroll
    for (int w = 0; w < 3; w++)
#pragma unroll
        for (int i = 0; i < 4; i++) { acc[w][i][0] = 0ull; acc[w][i][1] = 0ull; }

    for (int k0 = 0; k0 < DM; k0 += 16) {
        __syncthreads();
        *reinterpret_cast<float4*>(&xs[xr_r * XS_STRIDE + xr_c * 4]) = xr;
        *reinterpret_cast<float4*>(&ws[w_kk0 * WS_STRIDE + 0 * 68 + w_n4 * 4]) = wr0a;
        *reinterpret_cast<float4*>(&ws[w_kk1 * WS_STRIDE + 0 * 68 + w_n4 * 4]) = wr0b;
        *reinterpret_cast<float4*>(&ws[w_kk0 * WS_STRIDE + 1 * 68 + w_n4 * 4]) = wr1a;
        *reinterpret_cast<float4*>(&ws[w_kk1 * WS_STRIDE + 1 * 68 + w_n4 * 4]) = wr1b;
        *reinterpret_cast<float4*>(&ws[w_kk0 * WS_STRIDE + 2 * 68 + w_n4 * 4]) = wr2a;
        *reinterpret_cast<float4*>(&ws[w_kk1 * WS_STRIDE + 2 * 68 + w_n4 * 4]) = wr2b;
        __syncthreads();

        if (k0 + 16 < DM) {
            const int kn = k0 + 16;
            xr   = *reinterpret_cast<const float4*>(&x[(row0 + xr_r) * DM + kn + xr_c * 4]);
            wr0a = *reinterpret_cast<const float4*>(&Wp0[(kn + w_kk0) * DK + w_n4 * 4]);
            wr0b = *reinterpret_cast<const float4*>(&Wp0[(kn + w_kk1) * DK + w_n4 * 4]);
            wr1a = *reinterpret_cast<const float4*>(&Wp1[(kn + w_kk0) * DK + w_n4 * 4]);
            wr1b = *reinterpret_cast<const float4*>(&Wp1[(kn + w_kk1) * DK + w_n4 * 4]);
            wr2a = *reinterpret_cast<const float4*>(&Wp2[(kn + w_kk0) * DK + w_n4 * 4]);
            wr2b = *reinterpret_cast<const float4*>(&Wp2[(kn + w_kk1) * DK + w_n4 * 4]);
        }

#pragma unroll
        for (int kg = 0; kg < 4; kg++) {
            float4 av[4];
#pragma unroll
            for (int i = 0; i < 4; i++)
                av[i] = *reinterpret_cast<const float4*>(&xs[(ty * 4 + i) * XS_STRIDE + kg * 4]);
#pragma unroll
            for (int sub = 0; sub < 4; sub++) {
                const int kk = kg * 4 + sub;
                ulonglong2 b0 = *reinterpret_cast<const ulonglong2*>(&ws[kk * WS_STRIDE + 0 * 68 + tx * 4]);
                ulonglong2 b1 = *reinterpret_cast<const ulonglong2*>(&ws[kk * WS_STRIDE + 1 * 68 + tx * 4]);
                ulonglong2 b2 = *reinterpret_cast<const ulonglong2*>(&ws[kk * WS_STRIDE + 2 * 68 + tx * 4]);
#pragma unroll
                for (int i = 0; i < 4; i++) {
                    float q = (&av[i].x)[sub];
                    uint64_t a = f2u(q, q);
                    fma2(acc[0][i][0], a, b0.x); fma2(acc[0][i][1], a, b0.y);
                    fma2(acc[1][i][0], a, b1.x); fma2(acc[1][i][1], a, b1.y);
                    fma2(acc[2][i][0], a, b2.x); fma2(acc[2][i][1], a, b2.y);
                }
            }
        }
    }

    // Epilogue
    const int b  = row0 >> 12;          // 4096 rows per batch, 32 | 4096
    const int s0 = row0 & (S_ - 1);
    float kv[4][4];
#pragma unroll
    for (int i = 0; i < 4; i++) {
        const int r = row0 + ty * 4 + i;
        // Q (scaled by 0.125)
        float2 qa = u2f(acc[0][i][0]), qb = u2f(acc[0][i][1]);
        float4 qo = make_float4(qa.x * 0.125f, qa.y * 0.125f, qb.x * 0.125f, qb.y * 0.125f);
        *reinterpret_cast<float4*>(&g_Q[r * DK + tx * 4]) = qo;
        // V
        float2 va = u2f(acc[2][i][0]), vb = u2f(acc[2][i][1]);
        *reinterpret_cast<float4*>(&g_V[r * DK + tx * 4]) = make_float4(va.x, va.y, vb.x, vb.y);
        // K -> registers for transpose
        float2 ka = u2f(acc[1][i][0]), kb = u2f(acc[1][i][1]);
        kv[i][0] = ka.x; kv[i][1] = ka.y; kv[i][2] = kb.x; kv[i][3] = kb.y;
    }
#pragma unroll
    for (int c = 0; c < 4; c++) {
        float4 kc = make_float4(kv[0][c], kv[1][c], kv[2][c], kv[3][c]);
        *reinterpret_cast<float4*>(&g_Kt[(b * DK + tx * 4 + c) * S_ + s0 + ty * 4]) = kc;
    }
}

// =====================================================================
// Kernel 2: causal flash attention. grid = (128, 4), block = 128.
// ONE q-tile (BQ=32) per block; j = 127 - blockIdx.x so the longest
// blocks launch first (short blocks backfill the tail).
// 52KB smem + 128 regs -> 4 co-resident blocks/SM = 16 warps/SM.
// Thread (ty 0..7, tx 0..15) owns 4x4 of the 32x64 S / 32x64 O tiles.
// =====================================================================
#define TS 68                       // padded tile stride (floats)
#define OFF_QS 0                    // qs [32][TS]
#define OFF_KS (32 * TS)            // ks [64 d][TS keys]
#define OFF_VS (OFF_KS + 64 * TS)   // vs [64 s][TS d]
#define OFF_PS (OFF_VS + 64 * TS)   // ps [32 r][TS s]
#define SMEM_TOTAL ((OFF_PS + 32 * TS) * 4)   // 52224 bytes

__global__ __launch_bounds__(128, 4) void attn_kernel(float* __restrict__ out)
{
    extern __shared__ float sm[];
    float* qs = sm + OFF_QS;
    float* ks = sm + OFF_KS;
    float* vs = sm + OFF_VS;
    float* ps = sm + OFF_PS;

    const int tid = threadIdx.x;
    const int ty = tid >> 4;   // 0..7  -> rows ty*4..+3
    const int tx = tid & 15;   // 0..15 -> cols tx*4..+3
    const int b = blockIdx.y;
    const int j = 127 - (int)blockIdx.x;   // longest-first launch order
    const int q0 = j * 32;
    const int nkv = (j >> 1) + 1;

    const float* __restrict__ Qb  = g_Q  + b * (S_ * DK);
    const float* __restrict__ Ktb = g_Kt + b * (DK * S_);
    const float* __restrict__ Vb  = g_V  + b * (S_ * DK);

    // Load Q tile (32 x 64) row-major, already scaled
#pragma unroll
    for (int i = 0; i < 4; i++) {
        int lin = tid + i * 128;
        int d4 = lin & 15, r = lin >> 4;
        *reinterpret_cast<float4*>(&qs[r * TS + d4 * 4]) =
            *reinterpret_cast<const float4*>(&Qb[(q0 + r) * DK + d4 * 4]);
    }

    uint64_t o2[4][2];
    float m[4], l[4];
#pragma unroll
    for (int i = 0; i < 4; i++) {
        o2[i][0] = 0ull; o2[i][1] = 0ull;
        m[i] = -1e30f; l[i] = 0.0f;
    }

    for (int t = 0; t < nkv; t++) {
        const int k0 = t * 64;
        __syncthreads();   // ks/vs free for reuse (also covers qs on t=0)

        // K tile: ks[d][key] straight from g_Kt (coalesced, conflict-free)
        // V tile: vs[s][d] row-major
#pragma unroll
        for (int i = 0; i < 8; i++) {
            int lin = tid + i * 128;
            int c4 = lin & 15, rr = lin >> 4;   // rr: d for K, s for V
            *reinterpret_cast<float4*>(&ks[rr * TS + c4 * 4]) =
                *reinterpret_cast<const float4*>(&Ktb[rr * S_ + k0 + c4 * 4]);
            *reinterpret_cast<float4*>(&vs[rr * TS + c4 * 4]) =
                *reinterpret_cast<const float4*>(&Vb[(k0 + rr) * DK + c4 * 4]);
        }
        __syncthreads();

        // GEMM1: S = Q @ K^T (contract over d). Q via broadcast LDS + reg splat.
        uint64_t s2[4][2];
#pragma unroll
        for (int i = 0; i < 4; i++) { s2[i][0] = 0ull; s2[i][1] = 0ull; }
#pragma unroll
        for (int d0 = 0; d0 < 64; d0 += 4) {
            float4 qv[4];
#pragma unroll
            for (int i = 0; i < 4; i++)
                qv[i] = *reinterpret_cast<const float4*>(&qs[(ty * 4 + i) * TS + d0]);
#pragma unroll
            for (int sub = 0; sub < 4; sub++) {
                ulonglong2 kk = *reinterpret_cast<const ulonglong2*>(&ks[(d0 + sub) * TS + tx * 4]);
#pragma unroll
                for (int i = 0; i < 4; i++) {
                    float q = (&qv[i].x)[sub];
                    uint64_t a = f2u(q, q);
                    fma2(s2[i][0], a, kk.x); fma2(s2[i][1], a, kk.y);
                }
            }
        }

        // Online softmax update (per owned row)
        const bool maskt = (t == nkv - 1);
        float pp[4][4];
#pragma unroll
        for (int i = 0; i < 4; i++) {
            float2 a = u2f(s2[i][0]);
            float2 c = u2f(s2[i][1]);
            pp[i][0] = a.x; pp[i][1] = a.y; pp[i][2] = c.x; pp[i][3] = c.y;
            if (maskt) {
                int qrow = q0 + ty * 4 + i;
#pragma unroll
                for (int jn = 0; jn < 4; jn++)
                    if (k0 + tx * 4 + jn > qrow) pp[i][jn] = -1e30f;
            }
            float mi = fmaxf(fmaxf(pp[i][0], pp[i][1]), fmaxf(pp[i][2], pp[i][3]));
#pragma unroll
            for (int off = 8; off > 0; off >>= 1)
                mi = fmaxf(mi, __shfl_xor_sync(0xffffffffu, mi, off));
            float mnew = fmaxf(m[i], mi);
            float alpha = __expf(m[i] - mnew);
            float rs = 0.0f;
#pragma unroll
            for (int jn = 0; jn < 4; jn++) {
                float p = __expf(pp[i][jn] - mnew);
                pp[i][jn] = p;
                rs += p;
            }
#pragma unroll
            for (int off = 8; off > 0; off >>= 1)
                rs += __shfl_xor_sync(0xffffffffu, rs, off);
            l[i] = l[i] * alpha + rs;
            m[i] = mnew;
            uint64_t a2 = f2u(alpha, alpha);
            mul2(o2[i][0], a2); mul2(o2[i][1], a2);
        }

        // P store: plain row-major, conflict-free STS.128.
        // P rows are produced & consumed within the same warp -> syncwarp only.
#pragma unroll
        for (int i = 0; i < 4; i++)
            *reinterpret_cast<float4*>(&ps[(ty * 4 + i) * TS + tx * 4]) =
                make_float4(pp[i][0], pp[i][1], pp[i][2], pp[i][3]);
        __syncwarp();

        // GEMM2: O += P @ V (contract over s). P via broadcast LDS + reg splat.
#pragma unroll
        for (int s0 = 0; s0 < 64; s0 += 4) {
            float4 pv[4];
#pragma unroll
            for (int i = 0; i < 4; i++)
                pv[i] = *reinterpret_cast<const float4*>(&ps[(ty * 4 + i) * TS + s0]);
#pragma unroll
            for (int sub = 0; sub < 4; sub++) {
                ulonglong2 vv = *reinterpret_cast<const ulonglong2*>(&vs[(s0 + sub) * TS + tx * 4]);
#pragma unroll
                for (int i = 0; i < 4; i++) {
                    float p = (&pv[i].x)[sub];
                    uint64_t a = f2u(p, p);
                    fma2(o2[i][0], a, vv.x); fma2(o2[i][1], a, vv.y);
                }
            }
        }
    }

    // Epilogue: normalize and write out
#pragma unroll
    for (int i = 0; i < 4; i++) {
        float inv = 1.0f / l[i];
        uint64_t iv = f2u(inv, inv);
        mul2(o2[i][0], iv); mul2(o2[i][1], iv);
        ulonglong2 o; o.x = o2[i][0]; o.y = o2[i][1];
        *reinterpret_cast<ulonglong2*>(
            &out[((b * S_) + q0 + ty * 4 + i) * DK + tx * 4]) = o;
    }
}

// =====================================================================
extern "C" void kernel_launch(void* const* d_in, const int* in_sizes, int n_in,
                              void* d_out, int out_size)
{
    const float* x  = (const float*)d_in[0];
    const float* WQ = (const float*)d_in[1];
    const float* WK = (const float*)d_in[2];
    const float* WV = (const float*)d_in[3];
    float* out = (float*)d_out;

    (void)in_sizes; (void)n_in; (void)out_size;

    cudaFuncSetAttribute(attn_kernel, cudaFuncAttributeMaxDynamicSharedMemorySize, SMEM_TOTAL);

    proj_kernel<<<512, 128>>>(x, WQ, WK, WV);
    attn_kernel<<<dim3(128, 4), 128, SMEM_TOTAL>>>(out);
}

// round 4
// speedup vs baseline: 1.2715x; 1.2715x over previous
#include <cuda_runtime.h>
#include <cstdint>

#define B_  4
#define S_  4096
#define DM  768
#define DK  64
#define NS  4          // KV splits per q-tile

// Scratch (device globals: no allocation allowed)
__device__ float  g_Q [B_ * S_ * DK];   // [b*S+s][d]  (pre-scaled by 1/8)
__device__ float  g_Kt[B_ * DK * S_];   // [b][d][s]   (K transposed)
__device__ float  g_V [B_ * S_ * DK];   // [b*S+s][d]
__device__ float  g_Opart[B_ * NS * 128 * 32 * DK];  // unnormalized partial O
__device__ float2 g_ml   [B_ * NS * 128 * 32];       // per-row (m, l) per split

// ---------------- packed f32x2 helpers (FFMA2 path, sm_100+) ----------------
__device__ __forceinline__ void fma2(uint64_t& acc, uint64_t a, uint64_t b) {
    asm("fma.rn.f32x2 %0, %1, %2, %0;" : "+l"(acc) : "l"(a), "l"(b));
}
__device__ __forceinline__ void mul2(uint64_t& acc, uint64_t a) {
    asm("mul.rn.f32x2 %0, %0, %1;" : "+l"(acc) : "l"(a));
}
__device__ __forceinline__ uint64_t f2u(float x, float y) {
    uint64_t v; asm("mov.b64 %0, {%1,%2};" : "=l"(v) : "f"(x), "f"(y)); return v;
}
__device__ __forceinline__ float2 u2f(uint64_t v) {
    float2 f; asm("mov.b64 {%0,%1}, %2;" : "=f"(f.x), "=f"(f.y) : "l"(v)); return f;
}

// =====================================================================
// Kernel 1: fused QKV projection. grid = 256, block = 256. (round-2 version)
// One block computes a 64-row stripe of Q, K, V together (x read ONCE).
// K is written TRANSPOSED to g_Kt[b][d][s]; Q is pre-scaled by 0.125.
// =====================================================================
#define XS_STRIDE 20    // floats per x row (16 + 4 pad)
#define WS_STRIDE 208   // floats per kk row (3*68 + 4 pad)

__global__ __launch_bounds__(256) void proj_kernel(
    const float* __restrict__ x,
    const float* __restrict__ WQ,
    const float* __restrict__ WK,
    const float* __restrict__ WV)
{
    __shared__ float xs[64 * XS_STRIDE];   // [r][kk]
    __shared__ float ws[16 * WS_STRIDE];   // [kk][w*68 + n]

    const int tid = threadIdx.x;
    const int ty = tid >> 4;        // 0..15 -> rows ty*4..+3
    const int tx = tid & 15;        // 0..15 -> cols tx*4..+3
    const int row0 = blockIdx.x * 64;

    const float* __restrict__ Wp0 = WQ;
    const float* __restrict__ Wp1 = WK;
    const float* __restrict__ Wp2 = WV;

    const int xr_r = tid >> 2, xr_c = tid & 3;        // x: 64 rows x 4 float4
    const int w_kk = tid >> 4, w_n4 = tid & 15;       // W: 16 kk x 16 float4 (per W)

    float4 xr = *reinterpret_cast<const float4*>(&x[(row0 + xr_r) * DM + xr_c * 4]);
    float4 wr0 = *reinterpret_cast<const float4*>(&Wp0[w_kk * DK + w_n4 * 4]);
    float4 wr1 = *reinterpret_cast<const float4*>(&Wp1[w_kk * DK + w_n4 * 4]);
    float4 wr2 = *reinterpret_cast<const float4*>(&Wp2[w_kk * DK + w_n4 * 4]);

    uint64_t acc[3][4][2];
#pragma unroll
    for (int w = 0; w < 3; w++)
#pragma unroll
        for (int i = 0; i < 4; i++) { acc[w][i][0] = 0ull; acc[w][i][1] = 0ull; }

    for (int k0 = 0; k0 < DM; k0 += 16) {
        __syncthreads();
        *reinterpret_cast<float4*>(&xs[xr_r * XS_STRIDE + xr_c * 4]) = xr;
        *reinterpret_cast<float4*>(&ws[w_kk * WS_STRIDE + 0 * 68 + w_n4 * 4]) = wr0;
        *reinterpret_cast<float4*>(&ws[w_kk * WS_STRIDE + 1 * 68 + w_n4 * 4]) = wr1;
        *reinterpret_cast<float4*>(&ws[w_kk * WS_STRIDE + 2 * 68 + w_n4 * 4]) = wr2;
        __syncthreads();

        if (k0 + 16 < DM) {
            xr  = *reinterpret_cast<const float4*>(&x[(row0 + xr_r) * DM + k0 + 16 + xr_c * 4]);
            wr0 = *reinterpret_cast<const float4*>(&Wp0[(k0 + 16 + w_kk) * DK + w_n4 * 4]);
            wr1 = *reinterpret_cast<const float4*>(&Wp1[(k0 + 16 + w_kk) * DK + w_n4 * 4]);
            wr2 = *reinterpret_cast<const float4*>(&Wp2[(k0 + 16 + w_kk) * DK + w_n4 * 4]);
        }

#pragma unroll
        for (int kg = 0; kg < 4; kg++) {
            float4 av[4];
#pragma unroll
            for (int i = 0; i < 4; i++)
                av[i] = *reinterpret_cast<const float4*>(&xs[(ty * 4 + i) * XS_STRIDE + kg * 4]);
#pragma unroll
            for (int sub = 0; sub < 4; sub++) {
                const int kk = kg * 4 + sub;
                ulonglong2 b0 = *reinterpret_cast<const ulonglong2*>(&ws[kk * WS_STRIDE + 0 * 68 + tx * 4]);
                ulonglong2 b1 = *reinterpret_cast<const ulonglong2*>(&ws[kk * WS_STRIDE + 1 * 68 + tx * 4]);
                ulonglong2 b2 = *reinterpret_cast<const ulonglong2*>(&ws[kk * WS_STRIDE + 2 * 68 + tx * 4]);
#pragma unroll
                for (int i = 0; i < 4; i++) {
                    float q = (&av[i].x)[sub];
                    uint64_t a = f2u(q, q);
                    fma2(acc[0][i][0], a, b0.x); fma2(acc[0][i][1], a, b0.y);
                    fma2(acc[1][i][0], a, b1.x); fma2(acc[1][i][1], a, b1.y);
                    fma2(acc[2][i][0], a, b2.x); fma2(acc[2][i][1], a, b2.y);
                }
            }
        }
    }

    // Epilogue
    const int b  = row0 >> 12;          // 4096 rows per batch, 64 | 4096
    const int s0 = row0 & (S_ - 1);
    float kv[4][4];
#pragma unroll
    for (int i = 0; i < 4; i++) {
        const int r = row0 + ty * 4 + i;
        float2 qa = u2f(acc[0][i][0]), qb = u2f(acc[0][i][1]);
        float4 qo = make_float4(qa.x * 0.125f, qa.y * 0.125f, qb.x * 0.125f, qb.y * 0.125f);
        *reinterpret_cast<float4*>(&g_Q[r * DK + tx * 4]) = qo;
        float2 va = u2f(acc[2][i][0]), vb = u2f(acc[2][i][1]);
        *reinterpret_cast<float4*>(&g_V[r * DK + tx * 4]) = make_float4(va.x, va.y, vb.x, vb.y);
        float2 ka = u2f(acc[1][i][0]), kb = u2f(acc[1][i][1]);
        kv[i][0] = ka.x; kv[i][1] = ka.y; kv[i][2] = kb.x; kv[i][3] = kb.y;
    }
#pragma unroll
    for (int c = 0; c < 4; c++) {
        float4 kc = make_float4(kv[0][c], kv[1][c], kv[2][c], kv[3][c]);
        *reinterpret_cast<float4*>(&g_Kt[(b * DK + tx * 4 + c) * S_ + s0 + ty * 4]) = kc;
    }
}

// =====================================================================
// Kernel 2: split-KV causal flash attention. grid = (128, 4, NS), block = 128.
// q-tile j = blockIdx.x (BQ=32); split = blockIdx.z handles KV tiles
// [t0, t1) with per = ceil(nkv/NS) (max 17 tiles -> balanced blocks).
// Writes UNNORMALIZED partial O + (m, l) per row per split.
// 52KB smem + 128 regs -> 4 co-resident blocks/SM = 16 warps/SM.
// =====================================================================
#define TS 68                       // padded tile stride (floats)
#define OFF_QS 0                    // qs [32][TS]
#define OFF_KS (32 * TS)            // ks [64 d][TS keys]
#define OFF_VS (OFF_KS + 64 * TS)   // vs [64 s][TS d]
#define OFF_PS (OFF_VS + 64 * TS)   // ps [32 r][TS s]
#define SMEM_TOTAL ((OFF_PS + 32 * TS) * 4)   // 52224 bytes

__global__ __launch_bounds__(128, 4) void attn_kernel()
{
    extern __shared__ float sm[];
    float* qs = sm + OFF_QS;
    float* ks = sm + OFF_KS;
    float* vs = sm + OFF_VS;
    float* ps = sm + OFF_PS;

    const int tid = threadIdx.x;
    const int ty = tid >> 4;   // 0..7  -> rows ty*4..+3
    const int tx = tid & 15;   // 0..15 -> cols tx*4..+3
    const int b = blockIdx.y;
    const int j = blockIdx.x;
    const int split = blockIdx.z;
    const int q0 = j * 32;
    const int nkv = (j >> 1) + 1;
    const int per = (nkv + NS - 1) / NS;
    const int t0 = split * per;
    const int t1 = min(nkv, t0 + per);
    if (t0 >= t1) return;   // empty split (uniform across block)

    const float* __restrict__ Qb  = g_Q  + b * (S_ * DK);
    const float* __restrict__ Ktb = g_Kt + b * (DK * S_);
    const float* __restrict__ Vb  = g_V  + b * (S_ * DK);

    // Load Q tile (32 x 64) row-major, already scaled
#pragma unroll
    for (int i = 0; i < 4; i++) {
        int lin = tid + i * 128;
        int d4 = lin & 15, r = lin >> 4;
        *reinterpret_cast<float4*>(&qs[r * TS + d4 * 4]) =
            *reinterpret_cast<const float4*>(&Qb[(q0 + r) * DK + d4 * 4]);
    }

    uint64_t o2[4][2];
    float m[4], l[4];
#pragma unroll
    for (int i = 0; i < 4; i++) {
        o2[i][0] = 0ull; o2[i][1] = 0ull;
        m[i] = -1e30f; l[i] = 0.0f;
    }

    for (int t = t0; t < t1; t++) {
        const int k0 = t * 64;
        __syncthreads();   // ks/vs free for reuse (also covers qs on first iter)

        // K tile: ks[d][key] straight from g_Kt; V tile: vs[s][d]
#pragma unroll
        for (int i = 0; i < 8; i++) {
            int lin = tid + i * 128;
            int c4 = lin & 15, rr = lin >> 4;
            *reinterpret_cast<float4*>(&ks[rr * TS + c4 * 4]) =
                *reinterpret_cast<const float4*>(&Ktb[rr * S_ + k0 + c4 * 4]);
            *reinterpret_cast<float4*>(&vs[rr * TS + c4 * 4]) =
                *reinterpret_cast<const float4*>(&Vb[(k0 + rr) * DK + c4 * 4]);
        }
        __syncthreads();

        // GEMM1: S = Q @ K^T (contract over d)
        uint64_t s2[4][2];
#pragma unroll
        for (int i = 0; i < 4; i++) { s2[i][0] = 0ull; s2[i][1] = 0ull; }
#pragma unroll
        for (int d0 = 0; d0 < 64; d0 += 4) {
            float4 qv[4];
#pragma unroll
            for (int i = 0; i < 4; i++)
                qv[i] = *reinterpret_cast<const float4*>(&qs[(ty * 4 + i) * TS + d0]);
#pragma unroll
            for (int sub = 0; sub < 4; sub++) {
                ulonglong2 kk = *reinterpret_cast<const ulonglong2*>(&ks[(d0 + sub) * TS + tx * 4]);
#pragma unroll
                for (int i = 0; i < 4; i++) {
                    float q = (&qv[i].x)[sub];
                    uint64_t a = f2u(q, q);
                    fma2(s2[i][0], a, kk.x); fma2(s2[i][1], a, kk.y);
                }
            }
        }

        // Online softmax update (masking only at the global diagonal tile)
        const bool maskt = (t == nkv - 1);
        float pp[4][4];
#pragma unroll
        for (int i = 0; i < 4; i++) {
            float2 a = u2f(s2[i][0]);
            float2 c = u2f(s2[i][1]);
            pp[i][0] = a.x; pp[i][1] = a.y; pp[i][2] = c.x; pp[i][3] = c.y;
            if (maskt) {
                int qrow = q0 + ty * 4 + i;
#pragma unroll
                for (int jn = 0; jn < 4; jn++)
                    if (k0 + tx * 4 + jn > qrow) pp[i][jn] = -1e30f;
            }
            float mi = fmaxf(fmaxf(pp[i][0], pp[i][1]), fmaxf(pp[i][2], pp[i][3]));
#pragma unroll
            for (int off = 8; off > 0; off >>= 1)
                mi = fmaxf(mi, __shfl_xor_sync(0xffffffffu, mi, off));
            float mnew = fmaxf(m[i], mi);
            float alpha = __expf(m[i] - mnew);
            float rs = 0.0f;
#pragma unroll
            for (int jn = 0; jn < 4; jn++) {
                float p = __expf(pp[i][jn] - mnew);
                pp[i][jn] = p;
                rs += p;
            }
#pragma unroll
            for (int off = 8; off > 0; off >>= 1)
                rs += __shfl_xor_sync(0xffffffffu, rs, off);
            l[i] = l[i] * alpha + rs;
            m[i] = mnew;
            uint64_t a2 = f2u(alpha, alpha);
            mul2(o2[i][0], a2); mul2(o2[i][1], a2);
        }

        // P store (row-major, conflict-free); same-warp produce/consume
#pragma unroll
        for (int i = 0; i < 4; i++)
            *reinterpret_cast<float4*>(&ps[(ty * 4 + i) * TS + tx * 4]) =
                make_float4(pp[i][0], pp[i][1], pp[i][2], pp[i][3]);
        __syncwarp();

        // GEMM2: O += P @ V (contract over s)
#pragma unroll
        for (int s0 = 0; s0 < 64; s0 += 4) {
            float4 pv[4];
#pragma unroll
            for (int i = 0; i < 4; i++)
                pv[i] = *reinterpret_cast<const float4*>(&ps[(ty * 4 + i) * TS + s0]);
#pragma unroll
            for (int sub = 0; sub < 4; sub++) {
                ulonglong2 vv = *reinterpret_cast<const ulonglong2*>(&vs[(s0 + sub) * TS + tx * 4]);
#pragma unroll
                for (int i = 0; i < 4; i++) {
                    float p = (&pv[i].x)[sub];
                    uint64_t a = f2u(p, p);
                    fma2(o2[i][0], a, vv.x); fma2(o2[i][1], a, vv.y);
                }
            }
        }
    }

    // Epilogue: write UNNORMALIZED partial O + (m, l)
    const int base = ((b * NS + split) * 128 + j) * 32;
#pragma unroll
    for (int i = 0; i < 4; i++) {
        const int r = ty * 4 + i;
        ulonglong2 o; o.x = o2[i][0]; o.y = o2[i][1];
        *reinterpret_cast<ulonglong2*>(&g_Opart[(base + r) * DK + tx * 4]) = o;
        if (tx == 0) g_ml[base + r] = make_float2(m[i], l[i]);
    }
}

// =====================================================================
// Kernel 3: combine partials. grid = (128, 4), block = 128.
// Thread handles one row-quarter: r = tid>>2 (0..31), 16 cols.
// =====================================================================
__global__ __launch_bounds__(128) void combine_kernel(float* __restrict__ out)
{
    const int j = blockIdx.x, b = blockIdx.y;
    const int tid = threadIdx.x;
    const int r = tid >> 2;
    const int c0 = (tid & 3) * 16;
    const int nkv = (j >> 1) + 1;
    const int per = (nkv + NS - 1) / NS;
    const int nsp = (nkv + per - 1) / per;   // non-empty splits

    float mv[NS], lv[NS];
    float M = -1e30f;
    for (int s = 0; s < nsp; s++) {
        float2 ml = g_ml[((b * NS + s) * 128 + j) * 32 + r];
        mv[s] = ml.x; lv[s] = ml.y;
        M = fmaxf(M, mv[s]);
    }
    float L = 0.0f, w[NS];
    for (int s = 0; s < nsp; s++) {
        w[s] = __expf(mv[s] - M);
        L += w[s] * lv[s];
    }
    const float inv = 1.0f / L;

    float4 acc[4];
#pragma unroll
    for (int q = 0; q < 4; q++) acc[q] = make_float4(0.f, 0.f, 0.f, 0.f);

    for (int s = 0; s < nsp; s++) {
        const float* Op = &g_Opart[(((b * NS + s) * 128 + j) * 32 + r) * DK + c0];
        const float ws = w[s];
#pragma unroll
        for (int q = 0; q < 4; q++) {
            float4 v = *reinterpret_cast<const float4*>(Op + q * 4);
            acc[q].x += ws * v.x; acc[q].y += ws * v.y;
            acc[q].z += ws * v.z; acc[q].w += ws * v.w;
        }
    }

    float* op = &out[((b * S_) + j * 32 + r) * DK + c0];
#pragma unroll
    for (int q = 0; q < 4; q++) {
        float4 v = make_float4(acc[q].x * inv, acc[q].y * inv,
                               acc[q].z * inv, acc[q].w * inv);
        *reinterpret_cast<float4*>(op + q * 4) = v;
    }
}

// =====================================================================
extern "C" void kernel_launch(void* const* d_in, const int* in_sizes, int n_in,
                              void* d_out, int out_size)
{
    const float* x  = (const float*)d_in[0];
    const float* WQ = (const float*)d_in[1];
    const float* WK = (const float*)d_in[2];
    const float* WV = (const float*)d_in[3];
    float* out = (float*)d_out;

    (void)in_sizes; (void)n_in; (void)out_size;

    cudaFuncSetAttribute(attn_kernel, cudaFuncAttributeMaxDynamicSharedMemorySize, SMEM_TOTAL);

    proj_kernel<<<256, 256>>>(x, WQ, WK, WV);
    attn_kernel<<<dim3(128, 4, NS), 128, SMEM_TOTAL>>>();
    combine_kernel<<<dim3(128, 4), 128>>>(out);
}